// round 1
// baseline (speedup 1.0000x reference)
#include <cuda_runtime.h>
#include <math.h>

#define B_  8
#define T_  1024
#define C_  1024
#define H_  16
#define D_  64
#define M_  (B_*T_)    // 8192
#define HD_ (H_*D_)    // 1024

// Scratch (static device globals — no runtime allocation)
__device__ float g_q[B_*H_*T_*D_];
__device__ float g_k[B_*H_*T_*D_];
__device__ float g_v[B_*H_*T_*D_];
__device__ float g_att[M_*HD_];

// ---------------------------------------------------------------------------
// Kernel 1: fused QKV projection.
// C_tile = X[128 rows, 1024] @ W[1024, 128 cols], cols over 3*H*D = 3072.
// col n: type = n/1024 (q/k/v), h = (n%1024)/64, d = n%64; W elem (c,n) = Wt[h*C*D + c*D + d]
// ---------------------------------------------------------------------------
__global__ __launch_bounds__(256) void qkv_kernel(
    const float* __restrict__ x,
    const float* __restrict__ Wq,
    const float* __restrict__ Wk,
    const float* __restrict__ Wv)
{
    __shared__ float As[16][132];   // transposed: As[k][m], padded
    __shared__ float Bs[16][132];   // natural:    Bs[k][n], padded

    const int m0  = blockIdx.x * 128;
    const int n0  = blockIdx.y * 128;
    const int tid = threadIdx.x;
    const int tx  = tid & 15;
    const int ty  = tid >> 4;

    // B-load mapping: this thread loads column (n0+nb), k rows kb, kb+2, ...
    const int nb = tid & 127;
    const int kb = tid >> 7;
    const int ncol  = n0 + nb;
    const int btype = ncol >> 10;
    const float* Wt = (btype == 0) ? Wq : ((btype == 1) ? Wk : Wv);
    const int hh = (ncol & 1023) >> 6;
    const int dd = ncol & 63;
    const float* wcol = Wt + hh * (C_ * D_) + dd;   // elem at k: wcol[k*D_]

    // A-load mapping
    const int arow = tid >> 2;      // 0..63
    const int kvec = tid & 3;       // float4 index along k

    float acc[8][8];
#pragma unroll
    for (int i = 0; i < 8; i++)
#pragma unroll
        for (int j = 0; j < 8; j++) acc[i][j] = 0.0f;

    for (int k0 = 0; k0 < C_; k0 += 16) {
#pragma unroll
        for (int p = 0; p < 2; p++) {
            const int r = arow + p * 64;
            float4 v = *(const float4*)(x + (size_t)(m0 + r) * C_ + k0 + kvec * 4);
            As[kvec*4+0][r] = v.x;
            As[kvec*4+1][r] = v.y;
            As[kvec*4+2][r] = v.z;
            As[kvec*4+3][r] = v.w;
        }
#pragma unroll
        for (int i = 0; i < 8; i++) {
            const int kk = kb + i * 2;
            Bs[kk][nb] = wcol[(size_t)(k0 + kk) * D_];
        }
        __syncthreads();

#pragma unroll
        for (int kk = 0; kk < 16; kk++) {
            float4 a0 = *(const float4*)&As[kk][ty*4];
            float4 a1 = *(const float4*)&As[kk][64 + ty*4];
            float4 b0 = *(const float4*)&Bs[kk][tx*4];
            float4 b1 = *(const float4*)&Bs[kk][64 + tx*4];
            float a[8] = {a0.x,a0.y,a0.z,a0.w, a1.x,a1.y,a1.z,a1.w};
            float b[8] = {b0.x,b0.y,b0.z,b0.w, b1.x,b1.y,b1.z,b1.w};
#pragma unroll
            for (int i = 0; i < 8; i++)
#pragma unroll
                for (int j = 0; j < 8; j++)
                    acc[i][j] = fmaf(a[i], b[j], acc[i][j]);
        }
        __syncthreads();
    }

    // Writeback to Q/K/V in [B,H,T,D]
#pragma unroll
    for (int i = 0; i < 8; i++) {
        const int r  = m0 + ((i < 4) ? (ty*4 + i) : (64 + ty*4 + (i - 4)));
        const int bb = r >> 10;
        const int t  = r & 1023;
#pragma unroll
        for (int jj = 0; jj < 2; jj++) {
            const int n  = n0 + ((jj == 0) ? (tx*4) : (64 + tx*4));
            const int t2 = n >> 10;
            const int h2 = (n & 1023) >> 6;
            const int d2 = n & 63;
            float* dst = (t2 == 0) ? g_q : ((t2 == 1) ? g_k : g_v);
            float4 v = make_float4(acc[i][jj*4+0], acc[i][jj*4+1],
                                   acc[i][jj*4+2], acc[i][jj*4+3]);
            *(float4*)(dst + (size_t)(((bb*H_ + h2)*T_ + t)) * D_ + d2) = v;
        }
    }
}

// ---------------------------------------------------------------------------
// Kernel 2: causal flash attention per (b, h, query block of 64).
// smem: Qs^T[64][68], Ks^T[64][68], Ps^T[64][68], Vs[64][64]  = 68608 B dynamic
// 256 threads; thread (tx,ty) owns S/O rows ty*4..+3 and cols tx*4..+3.
// ---------------------------------------------------------------------------
#define QS 68

__global__ __launch_bounds__(256) void attn_kernel()
{
    extern __shared__ float sm[];
    float* Qs = sm;                 // [d][r]
    float* Ks = sm + 64*QS;         // [d][c]
    float* Ps = sm + 2*64*QS;       // [j][r]
    float* Vs = sm + 3*64*QS;       // [j][d] natural

    const int qb  = blockIdx.x;
    const int h   = blockIdx.y;
    const int b   = blockIdx.z;
    const int tid = threadIdx.x;
    const int tx  = tid & 15;
    const int ty  = tid >> 4;

    const size_t head_off = (size_t)(b*H_ + h) * T_ * D_;
    const float* Qg = g_q + head_off;
    const float* Kg = g_k + head_off;
    const float* Vg = g_v + head_off;

    // Load Q tile transposed
    {
        const int lr = tid >> 2, dseg = tid & 3;
        const float4* src = (const float4*)(Qg + (size_t)(qb*64 + lr) * D_ + dseg*16);
#pragma unroll
        for (int i = 0; i < 4; i++) {
            float4 v = src[i];
            const int d0 = dseg*16 + i*4;
            Qs[(d0+0)*QS + lr] = v.x;
            Qs[(d0+1)*QS + lr] = v.y;
            Qs[(d0+2)*QS + lr] = v.z;
            Qs[(d0+3)*QS + lr] = v.w;
        }
    }

    float acc[4][4];
#pragma unroll
    for (int i = 0; i < 4; i++)
#pragma unroll
        for (int j = 0; j < 4; j++) acc[i][j] = 0.0f;
    float mrow[4] = {-INFINITY, -INFINITY, -INFINITY, -INFINITY};
    float lrow[4] = {0.f, 0.f, 0.f, 0.f};

    const float scale = 0.125f;     // D^-0.5
    const int qr0 = qb*64 + ty*4;

    for (int kt = 0; kt <= qb; kt++) {
        // Load K (transposed) + V (natural) tiles
        {
            const int lr = tid >> 2, dseg = tid & 3;
            const float4* srcK = (const float4*)(Kg + (size_t)(kt*64 + lr) * D_ + dseg*16);
            const float4* srcV = (const float4*)(Vg + (size_t)(kt*64 + lr) * D_ + dseg*16);
#pragma unroll
            for (int i = 0; i < 4; i++) {
                float4 v = srcK[i];
                const int d0 = dseg*16 + i*4;
                Ks[(d0+0)*QS + lr] = v.x;
                Ks[(d0+1)*QS + lr] = v.y;
                Ks[(d0+2)*QS + lr] = v.z;
                Ks[(d0+3)*QS + lr] = v.w;
            }
            float4* dstV = (float4*)(Vs + lr*64 + dseg*16);
#pragma unroll
            for (int i = 0; i < 4; i++) dstV[i] = srcV[i];
        }
        __syncthreads();

        // S = Q K^T (4x4 per thread)
        float s[4][4];
#pragma unroll
        for (int i = 0; i < 4; i++)
#pragma unroll
            for (int j = 0; j < 4; j++) s[i][j] = 0.0f;
#pragma unroll
        for (int d = 0; d < 64; d++) {
            float4 a4 = *(const float4*)&Qs[d*QS + ty*4];
            float4 b4 = *(const float4*)&Ks[d*QS + tx*4];
            float a[4] = {a4.x, a4.y, a4.z, a4.w};
            float bb4[4] = {b4.x, b4.y, b4.z, b4.w};
#pragma unroll
            for (int i = 0; i < 4; i++)
#pragma unroll
                for (int j = 0; j < 4; j++)
                    s[i][j] = fmaf(a[i], bb4[j], s[i][j]);
        }

        // scale + causal mask
        const int kc0 = kt*64 + tx*4;
#pragma unroll
        for (int i = 0; i < 4; i++)
#pragma unroll
            for (int j = 0; j < 4; j++)
                s[i][j] = (kc0 + j <= qr0 + i) ? s[i][j] * scale : -INFINITY;

        // online softmax
        float mnew[4], lsum[4];
#pragma unroll
        for (int i = 0; i < 4; i++) {
            float tm = fmaxf(fmaxf(s[i][0], s[i][1]), fmaxf(s[i][2], s[i][3]));
#pragma unroll
            for (int o = 8; o >= 1; o >>= 1)
                tm = fmaxf(tm, __shfl_xor_sync(0xffffffffu, tm, o));
            mnew[i] = fmaxf(mrow[i], tm);
            float ls = 0.0f;
#pragma unroll
            for (int j = 0; j < 4; j++) {
                float p = __expf(s[i][j] - mnew[i]);
                s[i][j] = p;
                ls += p;
            }
#pragma unroll
            for (int o = 8; o >= 1; o >>= 1)
                ls += __shfl_xor_sync(0xffffffffu, ls, o);
            lsum[i] = ls;
        }
#pragma unroll
        for (int i = 0; i < 4; i++) {
            const float f = __expf(mrow[i] - mnew[i]);   // 0 on first tile
            lrow[i] = lrow[i] * f + lsum[i];
            mrow[i] = mnew[i];
#pragma unroll
            for (int k = 0; k < 4; k++) acc[i][k] *= f;
        }

        // P -> smem (transposed [j][r])
#pragma unroll
        for (int jj = 0; jj < 4; jj++)
#pragma unroll
            for (int i = 0; i < 4; i++)
                Ps[(tx*4 + jj)*QS + (ty*4 + i)] = s[i][jj];
        __syncthreads();

        // O += P V (masked entries are exactly 0, safe to run full 64)
#pragma unroll
        for (int j = 0; j < 64; j++) {
            float4 a4 = *(const float4*)&Ps[j*QS + ty*4];
            float4 b4 = *(const float4*)&Vs[j*64 + tx*4];
            float a[4] = {a4.x, a4.y, a4.z, a4.w};
            float bb4[4] = {b4.x, b4.y, b4.z, b4.w};
#pragma unroll
            for (int i = 0; i < 4; i++)
#pragma unroll
                for (int k = 0; k < 4; k++)
                    acc[i][k] = fmaf(a[i], bb4[k], acc[i][k]);
        }
        __syncthreads();
    }

    // Epilogue: normalize and write att[b*T + t][h*64 + d]
#pragma unroll
    for (int i = 0; i < 4; i++) {
        const float inv = 1.0f / lrow[i];
        const int t = qb*64 + ty*4 + i;
        float4 v = make_float4(acc[i][0]*inv, acc[i][1]*inv,
                               acc[i][2]*inv, acc[i][3]*inv);
        *(float4*)(g_att + (size_t)(b*T_ + t) * HD_ + h*64 + tx*4) = v;
    }
}

// ---------------------------------------------------------------------------
// Kernel 3: output projection. out = att[8192,1024] @ Wproj[1024,1024] + bias
// ---------------------------------------------------------------------------
__global__ __launch_bounds__(256) void proj_kernel(
    const float* __restrict__ Wp,
    const float* __restrict__ bias,
    float* __restrict__ out)
{
    __shared__ float As[16][132];
    __shared__ float Bs[16][132];

    const int m0  = blockIdx.x * 128;
    const int n0  = blockIdx.y * 128;
    const int tid = threadIdx.x;
    const int tx  = tid & 15;
    const int ty  = tid >> 4;

    const int nb = tid & 127;
    const int kb = tid >> 7;
    const int arow = tid >> 2;
    const int kvec = tid & 3;

    float acc[8][8];
#pragma unroll
    for (int i = 0; i < 8; i++)
#pragma unroll
        for (int j = 0; j < 8; j++) acc[i][j] = 0.0f;

    for (int k0 = 0; k0 < HD_; k0 += 16) {
#pragma unroll
        for (int p = 0; p < 2; p++) {
            const int r = arow + p * 64;
            float4 v = *(const float4*)(g_att + (size_t)(m0 + r) * HD_ + k0 + kvec * 4);
            As[kvec*4+0][r] = v.x;
            As[kvec*4+1][r] = v.y;
            As[kvec*4+2][r] = v.z;
            As[kvec*4+3][r] = v.w;
        }
#pragma unroll
        for (int i = 0; i < 8; i++) {
            const int kk = kb + i * 2;
            Bs[kk][nb] = Wp[(size_t)(k0 + kk) * C_ + n0 + nb];
        }
        __syncthreads();

#pragma unroll
        for (int kk = 0; kk < 16; kk++) {
            float4 a0 = *(const float4*)&As[kk][ty*4];
            float4 a1 = *(const float4*)&As[kk][64 + ty*4];
            float4 b0 = *(const float4*)&Bs[kk][tx*4];
            float4 b1 = *(const float4*)&Bs[kk][64 + tx*4];
            float a[8] = {a0.x,a0.y,a0.z,a0.w, a1.x,a1.y,a1.z,a1.w};
            float b[8] = {b0.x,b0.y,b0.z,b0.w, b1.x,b1.y,b1.z,b1.w};
#pragma unroll
            for (int i = 0; i < 8; i++)
#pragma unroll
                for (int j = 0; j < 8; j++)
                    acc[i][j] = fmaf(a[i], b[j], acc[i][j]);
        }
        __syncthreads();
    }

#pragma unroll
    for (int i = 0; i < 8; i++) {
        const int r = m0 + ((i < 4) ? (ty*4 + i) : (64 + ty*4 + (i - 4)));
#pragma unroll
        for (int jj = 0; jj < 2; jj++) {
            const int n = n0 + ((jj == 0) ? (tx*4) : (64 + tx*4));
            float4 bv = *(const float4*)(bias + n);
            float4 v = make_float4(acc[i][jj*4+0] + bv.x, acc[i][jj*4+1] + bv.y,
                                   acc[i][jj*4+2] + bv.z, acc[i][jj*4+3] + bv.w);
            *(float4*)(out + (size_t)r * C_ + n) = v;
        }
    }
}

// ---------------------------------------------------------------------------
extern "C" void kernel_launch(void* const* d_in, const int* in_sizes, int n_in,
                              void* d_out, int out_size)
{
    (void)in_sizes; (void)n_in; (void)out_size;
    const float* x    = (const float*)d_in[0];
    const float* Wq   = (const float*)d_in[1];
    const float* Wk   = (const float*)d_in[2];
    const float* Wv   = (const float*)d_in[3];
    const float* Wp   = (const float*)d_in[4];
    const float* bias = (const float*)d_in[5];
    float* out = (float*)d_out;

    const int attn_smem = (3 * 64 * QS + 64 * 64) * (int)sizeof(float);  // 68608 B
    cudaFuncSetAttribute(attn_kernel, cudaFuncAttributeMaxDynamicSharedMemorySize, attn_smem);

    qkv_kernel<<<dim3(64, 24), 256>>>(x, Wq, Wk, Wv);
    attn_kernel<<<dim3(16, 16, 8), 256, attn_smem>>>();
    proj_kernel<<<dim3(64, 8), 256>>>(Wp, bias, out);
}

// round 4
// speedup vs baseline: 1.6268x; 1.6268x over previous
#include <cuda_runtime.h>
#include <cuda_bf16.h>
#include <math.h>
#include <cstdint>

#define B_  8
#define T_  1024
#define C_  1024
#define H_  16
#define D_  64
#define M_  (B_*T_)    // 8192
#define HD_ (H_*D_)    // 1024
#define NQKV_ (3*HD_)  // 3072

// ---------------- scratch (static device globals) ----------------
__device__ unsigned short g_xhi[M_*C_],  g_xlo[M_*C_];       // x split  [M][K]
__device__ unsigned short g_bhi[NQKV_*C_], g_blo[NQKV_*C_];  // qkv W as B[n][k]
__device__ unsigned short g_phi[C_*HD_], g_plo[C_*HD_];      // proj W as B[n][k]
__device__ unsigned short g_atthi[M_*HD_], g_attlo[M_*HD_];  // attn out split [M][HD]
__device__ float g_q[B_*H_*T_*D_];
__device__ float g_k[B_*H_*T_*D_];
__device__ float g_v[B_*H_*T_*D_];

// ---------------- helpers ----------------
__device__ __forceinline__ uint32_t smem_u32(const void* p) {
    uint32_t a;
    asm("{ .reg .u64 t; cvta.to.shared.u64 t, %1; cvt.u32.u64 %0, t; }" : "=r"(a) : "l"(p));
    return a;
}
__device__ __forceinline__ void cp16(uint32_t dst, const void* src) {
    asm volatile("cp.async.cg.shared.global [%0], [%1], 16;" :: "r"(dst), "l"(src));
}
#define CP_COMMIT() asm volatile("cp.async.commit_group;" ::: "memory")
#define CP_WAIT1()  asm volatile("cp.async.wait_group 1;" ::: "memory")
#define CP_WAIT0()  asm volatile("cp.async.wait_group 0;" ::: "memory")

__device__ __forceinline__ void ldsm_x4(uint32_t* r, uint32_t addr) {
    asm volatile("ldmatrix.sync.aligned.m8n8.x4.shared.b16 {%0,%1,%2,%3}, [%4];"
        : "=r"(r[0]), "=r"(r[1]), "=r"(r[2]), "=r"(r[3]) : "r"(addr));
}
__device__ __forceinline__ void mma16816(float* d, const uint32_t* a, const uint32_t* b) {
    asm volatile("mma.sync.aligned.m16n8k16.row.col.f32.bf16.bf16.f32 "
        "{%0,%1,%2,%3}, {%4,%5,%6,%7}, {%8,%9}, {%0,%1,%2,%3};"
        : "+f"(d[0]), "+f"(d[1]), "+f"(d[2]), "+f"(d[3])
        : "r"(a[0]), "r"(a[1]), "r"(a[2]), "r"(a[3]), "r"(b[0]), "r"(b[1]));
}

__device__ __forceinline__ void split_bf16(float v, __nv_bfloat16& hi, __nv_bfloat16& lo) {
    hi = __float2bfloat16(v);
    lo = __float2bfloat16(v - __bfloat162float(hi));
}

// ---------------------------------------------------------------------------
// Conversion kernels
// ---------------------------------------------------------------------------
__global__ __launch_bounds__(256) void convx_kernel(const float* __restrict__ x) {
    int i = blockIdx.x * 256 + threadIdx.x;           // float4 index
    float4 v = ((const float4*)x)[i];
    __nv_bfloat16 h[4], l[4];
    split_bf16(v.x, h[0], l[0]); split_bf16(v.y, h[1], l[1]);
    split_bf16(v.z, h[2], l[2]); split_bf16(v.w, h[3], l[3]);
    __nv_bfloat162* ph = (__nv_bfloat162*)g_xhi;
    __nv_bfloat162* pl = (__nv_bfloat162*)g_xlo;
    ph[i*2]   = __nv_bfloat162(h[0], h[1]);
    ph[i*2+1] = __nv_bfloat162(h[2], h[3]);
    pl[i*2]   = __nv_bfloat162(l[0], l[1]);
    pl[i*2+1] = __nv_bfloat162(l[2], l[3]);
}

// W [H][C][D] -> B[n = n0 + h*64 + d][k]
__global__ __launch_bounds__(256) void convw_kernel(const float* __restrict__ W, int n0) {
    __shared__ float tile[32][65];
    const int h = blockIdx.x, kt = blockIdx.y;
    const int tid = threadIdx.x;
    const float* src = W + (size_t)h * (C_ * D_) + (size_t)kt * 32 * D_;
#pragma unroll
    for (int i = 0; i < 8; i++) {
        int u = i * 256 + tid;
        tile[u >> 6][u & 63] = src[(size_t)(u >> 6) * D_ + (u & 63)];
    }
    __syncthreads();
    const int d = tid >> 2, seg = tid & 3;
    __nv_bfloat162* dh = (__nv_bfloat162*)(g_bhi + (size_t)(n0 + h*64 + d) * C_ + kt*32 + seg*8);
    __nv_bfloat162* dl = (__nv_bfloat162*)(g_blo + (size_t)(n0 + h*64 + d) * C_ + kt*32 + seg*8);
#pragma unroll
    for (int j = 0; j < 4; j++) {
        __nv_bfloat16 h0, l0, h1, l1;
        split_bf16(tile[seg*8 + j*2][d],     h0, l0);
        split_bf16(tile[seg*8 + j*2 + 1][d], h1, l1);
        dh[j] = __nv_bfloat162(h0, h1);
        dl[j] = __nv_bfloat162(l0, l1);
    }
}

// Wproj [k][n] -> Bp[n][k]
__global__ __launch_bounds__(256) void convwp_kernel(const float* __restrict__ Wp) {
    __shared__ float tile[32][33];
    const int bx = blockIdx.x, by = blockIdx.y;
    const int tx = threadIdx.x & 31, ty = threadIdx.x >> 5;
#pragma unroll
    for (int r = 0; r < 4; r++)
        tile[ty + 8*r][tx] = Wp[(size_t)(by*32 + ty + 8*r) * C_ + bx*32 + tx];
    __syncthreads();
#pragma unroll
    for (int r = 0; r < 4; r++) {
        float v = tile[tx][ty + 8*r];
        __nv_bfloat16 hi, lo; split_bf16(v, hi, lo);
        size_t idx = (size_t)(bx*32 + ty + 8*r) * C_ + by*32 + tx;
        ((__nv_bfloat16*)g_phi)[idx] = hi;
        ((__nv_bfloat16*)g_plo)[idx] = lo;
    }
}

// ---------------------------------------------------------------------------
// mma.sync split-bf16 GEMM: C[128x128 tile] = A[M,1024] * B[n,1024]^T
// MODE 0: A = x split, B = qkv W -> g_q/g_k/g_v.  MODE 1: A = att, B = proj -> out+bias.
// smem per stage: Ahi|Alo (128 rows x 144B) + Bhi|Blo (128 rows x 144B) = 73728B; 2 stages.
// rows padded to 144B: ldmatrix row addresses stride 36 words -> banks r*4 mod 32, distinct.
// ---------------------------------------------------------------------------
#define ROWB        144
#define OP_BYTES    (128*ROWB)      // 18432
#define OFF_AHI     0
#define OFF_ALO     OP_BYTES
#define OFF_BHI     (2*OP_BYTES)
#define OFF_BLO     (3*OP_BYTES)
#define STAGE_BYTES (4*OP_BYTES)    // 73728
#define GEMM_SMEM   (2*STAGE_BYTES) // 147456
#define NCHUNK      16

template<int MODE>
__global__ __launch_bounds__(256, 1) void gemm_kernel(const float* __restrict__ bias,
                                                      float* __restrict__ out) {
    extern __shared__ char smem[];
    const int tid  = threadIdx.x;
    const int wid  = tid >> 5;
    const int lane = tid & 31;
    const int m0 = blockIdx.x * 128;
    const int n0 = blockIdx.y * 128;

    const __nv_bfloat16* Ahi = (MODE == 0) ? (const __nv_bfloat16*)g_xhi : (const __nv_bfloat16*)g_atthi;
    const __nv_bfloat16* Alo = (MODE == 0) ? (const __nv_bfloat16*)g_xlo : (const __nv_bfloat16*)g_attlo;
    const __nv_bfloat16* Bhi = (MODE == 0) ? (const __nv_bfloat16*)g_bhi : (const __nv_bfloat16*)g_phi;
    const __nv_bfloat16* Blo = (MODE == 0) ? (const __nv_bfloat16*)g_blo : (const __nv_bfloat16*)g_plo;

    const uint32_t sb0 = smem_u32(smem);

    // ---- pipeline load of one k-chunk (64 k) into stage s ----
    auto load_stage = [&](int c, int s) {
        const uint32_t base = sb0 + s * STAGE_BYTES;
        const int k0 = c * 64;
        const int row = tid >> 3;            // 0..31 step by +32 below? no: u-based
#pragma unroll
        for (int i = 0; i < 4; i++) {
            int u = i * 256 + tid;           // 0..1023: 16B chunk id
            int r = u >> 3, kc = (u & 7) * 8;
            uint32_t doff = r * ROWB + (u & 7) * 16;
            cp16(base + OFF_AHI + doff, Ahi + (size_t)(m0 + r) * C_ + k0 + kc);
            cp16(base + OFF_ALO + doff, Alo + (size_t)(m0 + r) * C_ + k0 + kc);
            cp16(base + OFF_BHI + doff, Bhi + (size_t)(n0 + r) * C_ + k0 + kc);
            cp16(base + OFF_BLO + doff, Blo + (size_t)(n0 + r) * C_ + k0 + kc);
        }
        (void)row;
    };

    const int warp_m = wid & 3;      // 4 x 32 rows
    const int warp_n = wid >> 2;     // 2 x 64 cols
    const int mati = lane >> 3;      // ldmatrix sub-matrix index
    const int ri   = lane & 7;

    float acc[2][8][4];
#pragma unroll
    for (int a = 0; a < 2; a++)
#pragma unroll
        for (int b = 0; b < 8; b++)
#pragma unroll
            for (int c = 0; c < 4; c++) acc[a][b][c] = 0.0f;

    load_stage(0, 0); CP_COMMIT();
    load_stage(1, 1); CP_COMMIT();

    for (int c = 0; c < NCHUNK; c++) {
        if (c < NCHUNK - 1) CP_WAIT1(); else CP_WAIT0();
        __syncthreads();

        const uint32_t base = sb0 + (c & 1) * STAGE_BYTES;
#pragma unroll
        for (int kc = 0; kc < 64; kc += 16) {
            // A fragments (2 m16 tiles x {hi,lo})
            uint32_t ah[2][4], al[2][4];
#pragma unroll
            for (int mt = 0; mt < 2; mt++) {
                int row = warp_m*32 + mt*16 + ri + (mati & 1) * 8;
                int kk  = kc + (mati >> 1) * 8;
                ldsm_x4(ah[mt], base + OFF_AHI + row * ROWB + kk * 2);
                ldsm_x4(al[mt], base + OFF_ALO + row * ROWB + kk * 2);
            }
            // B fragments (4 n16 tiles x {hi,lo}); mats: (n0-7,k0),(n0-7,k8),(n8-15,k0),(n8-15,k8)
            uint32_t bh[4][4], bl[4][4];
#pragma unroll
            for (int nt4 = 0; nt4 < 4; nt4++) {
                int n  = warp_n*64 + nt4*16 + ri + (mati >> 1) * 8;
                int kk = kc + (mati & 1) * 8;
                ldsm_x4(bh[nt4], base + OFF_BHI + n * ROWB + kk * 2);
                ldsm_x4(bl[nt4], base + OFF_BLO + n * ROWB + kk * 2);
            }
            // 3-pass split MMA: hi*hi + hi*lo + lo*hi
#pragma unroll
            for (int mt = 0; mt < 2; mt++)
#pragma unroll
                for (int nt = 0; nt < 8; nt++) {
                    uint32_t* bhf = &bh[nt >> 1][(nt & 1) * 2];
                    uint32_t* blf = &bl[nt >> 1][(nt & 1) * 2];
                    mma16816(acc[mt][nt], ah[mt], bhf);
                    mma16816(acc[mt][nt], ah[mt], blf);
                    mma16816(acc[mt][nt], al[mt], bhf);
                }
        }
        __syncthreads();
        if (c + 2 < NCHUNK) { load_stage(c + 2, c & 1); CP_COMMIT(); }
    }

    // ---- epilogue ----
    const int r4 = lane >> 2;            // row within m16 tile
    const int c2 = (lane & 3) * 2;       // col pair within n8 tile
#pragma unroll
    for (int mt = 0; mt < 2; mt++) {
#pragma unroll
        for (int nt = 0; nt < 8; nt++) {
            const int n = n0 + warp_n*64 + nt*8 + c2;
#pragma unroll
            for (int half = 0; half < 2; half++) {
                const int row = m0 + warp_m*32 + mt*16 + r4 + half*8;
                float2 v = make_float2(acc[mt][nt][half*2], acc[mt][nt][half*2 + 1]);
                if (MODE == 0) {
                    const int type = n >> 10;
                    float* dst = (type == 0) ? g_q : ((type == 1) ? g_k : g_v);
                    const int bb = row >> 10, tt = row & 1023;
                    const int h2 = (n & 1023) >> 6, d2 = n & 63;
                    *(float2*)(dst + (size_t)(((bb*H_ + h2)*T_ + tt)) * D_ + d2) = v;
                } else {
                    float2 bv = *(const float2*)(bias + n);
                    v.x += bv.x; v.y += bv.y;
                    *(float2*)(out + (size_t)row * C_ + n) = v;
                }
            }
        }
    }
}

// ---------------------------------------------------------------------------
// Causal flash attention (fp32 SIMT, validated round 1), split-bf16 epilogue.
// ---------------------------------------------------------------------------
#define QS 68

__global__ __launch_bounds__(256) void attn_kernel() {
    extern __shared__ float sm[];
    float* Qs = sm;                 // [d][r]
    float* Ks = sm + 64*QS;         // [d][c]
    float* Ps = sm + 2*64*QS;       // [j][r]
    float* Vs = sm + 3*64*QS;       // [j][d]

    const int qb  = blockIdx.x;
    const int h   = blockIdx.y;
    const int b   = blockIdx.z;
    const int tid = threadIdx.x;
    const int tx  = tid & 15;
    const int ty  = tid >> 4;

    const size_t head_off = (size_t)(b*H_ + h) * T_ * D_;
    const float* Qg = g_q + head_off;
    const float* Kg = g_k + head_off;
    const float* Vg = g_v + head_off;

    {
        const int lr = tid >> 2, dseg = tid & 3;
        const float4* src = (const float4*)(Qg + (size_t)(qb*64 + lr) * D_ + dseg*16);
#pragma unroll
        for (int i = 0; i < 4; i++) {
            float4 v = src[i];
            const int d0 = dseg*16 + i*4;
            Qs[(d0+0)*QS + lr] = v.x; Qs[(d0+1)*QS + lr] = v.y;
            Qs[(d0+2)*QS + lr] = v.z; Qs[(d0+3)*QS + lr] = v.w;
        }
    }

    float acc[4][4];
#pragma unroll
    for (int i = 0; i < 4; i++)
#pragma unroll
        for (int j = 0; j < 4; j++) acc[i][j] = 0.0f;
    float mrow[4] = {-INFINITY, -INFINITY, -INFINITY, -INFINITY};
    float lrow[4] = {0.f, 0.f, 0.f, 0.f};

    const float scale = 0.125f;
    const int qr0 = qb*64 + ty*4;

    for (int kt = 0; kt <= qb; kt++) {
        {
            const int lr = tid >> 2, dseg = tid & 3;
            const float4* srcK = (const float4*)(Kg + (size_t)(kt*64 + lr) * D_ + dseg*16);
            const float4* srcV = (const float4*)(Vg + (size_t)(kt*64 + lr) * D_ + dseg*16);
#pragma unroll
            for (int i = 0; i < 4; i++) {
                float4 v = srcK[i];
                const int d0 = dseg*16 + i*4;
                Ks[(d0+0)*QS + lr] = v.x; Ks[(d0+1)*QS + lr] = v.y;
                Ks[(d0+2)*QS + lr] = v.z; Ks[(d0+3)*QS + lr] = v.w;
            }
            float4* dstV = (float4*)(Vs + lr*64 + dseg*16);
#pragma unroll
            for (int i = 0; i < 4; i++) dstV[i] = srcV[i];
        }
        __syncthreads();

        float s[4][4];
#pragma unroll
        for (int i = 0; i < 4; i++)
#pragma unroll
            for (int j = 0; j < 4; j++) s[i][j] = 0.0f;
#pragma unroll
        for (int d = 0; d < 64; d++) {
            float4 a4 = *(const float4*)&Qs[d*QS + ty*4];
            float4 b4 = *(const float4*)&Ks[d*QS + tx*4];
            float a[4] = {a4.x, a4.y, a4.z, a4.w};
            float bb4[4] = {b4.x, b4.y, b4.z, b4.w};
#pragma unroll
            for (int i = 0; i < 4; i++)
#pragma unroll
                for (int j = 0; j < 4; j++)
                    s[i][j] = fmaf(a[i], bb4[j], s[i][j]);
        }

        const int kc0 = kt*64 + tx*4;
#pragma unroll
        for (int i = 0; i < 4; i++)
#pragma unroll
            for (int j = 0; j < 4; j++)
                s[i][j] = (kc0 + j <= qr0 + i) ? s[i][j] * scale : -INFINITY;

        float mnew[4], lsum[4];
#pragma unroll
        for (int i = 0; i < 4; i++) {
            float tm = fmaxf(fmaxf(s[i][0], s[i][1]), fmaxf(s[i][2], s[i][3]));
#pragma unroll
            for (int o = 8; o >= 1; o >>= 1)
                tm = fmaxf(tm, __shfl_xor_sync(0xffffffffu, tm, o));
            mnew[i] = fmaxf(mrow[i], tm);
            float ls = 0.0f;
#pragma unroll
            for (int j = 0; j < 4; j++) {
                float p = __expf(s[i][j] - mnew[i]);
                s[i][j] = p;
                ls += p;
            }
#pragma unroll
            for (int o = 8; o >= 1; o >>= 1)
                ls += __shfl_xor_sync(0xffffffffu, ls, o);
            lsum[i] = ls;
        }
#pragma unroll
        for (int i = 0; i < 4; i++) {
            const float f = __expf(mrow[i] - mnew[i]);
            lrow[i] = lrow[i] * f + lsum[i];
            mrow[i] = mnew[i];
#pragma unroll
            for (int k = 0; k < 4; k++) acc[i][k] *= f;
        }

#pragma unroll
        for (int jj = 0; jj < 4; jj++)
#pragma unroll
            for (int i = 0; i < 4; i++)
                Ps[(tx*4 + jj)*QS + (ty*4 + i)] = s[i][jj];
        __syncthreads();

#pragma unroll
        for (int j = 0; j < 64; j++) {
            float4 a4 = *(const float4*)&Ps[j*QS + ty*4];
            float4 b4 = *(const float4*)&Vs[j*64 + tx*4];
            float a[4] = {a4.x, a4.y, a4.z, a4.w};
            float bb4[4] = {b4.x, b4.y, b4.z, b4.w};
#pragma unroll
            for (int i = 0; i < 4; i++)
#pragma unroll
                for (int k = 0; k < 4; k++)
                    acc[i][k] = fmaf(a[i], bb4[k], acc[i][k]);
        }
        __syncthreads();
    }

    // Epilogue: normalize + bf16 hi/lo split into g_atthi/g_attlo [M][HD]
#pragma unroll
    for (int i = 0; i < 4; i++) {
        const float inv = 1.0f / lrow[i];
        const int t = qb*64 + ty*4 + i;
        const size_t base = (size_t)(b*T_ + t) * HD_ + h*64 + tx*4;
        float o[4] = {acc[i][0]*inv, acc[i][1]*inv, acc[i][2]*inv, acc[i][3]*inv};
        __nv_bfloat16 hi[4], lo[4];
#pragma unroll
        for (int j = 0; j < 4; j++) split_bf16(o[j], hi[j], lo[j]);
        __nv_bfloat162* dh = (__nv_bfloat162*)((__nv_bfloat16*)g_atthi + base);
        __nv_bfloat162* dl = (__nv_bfloat162*)((__nv_bfloat16*)g_attlo + base);
        dh[0] = __nv_bfloat162(hi[0], hi[1]); dh[1] = __nv_bfloat162(hi[2], hi[3]);
        dl[0] = __nv_bfloat162(lo[0], lo[1]); dl[1] = __nv_bfloat162(lo[2], lo[3]);
    }
}

// ---------------------------------------------------------------------------
extern "C" void kernel_launch(void* const* d_in, const int* in_sizes, int n_in,
                              void* d_out, int out_size)
{
    (void)in_sizes; (void)n_in; (void)out_size;
    const float* x    = (const float*)d_in[0];
    const float* Wq   = (const float*)d_in[1];
    const float* Wk   = (const float*)d_in[2];
    const float* Wv   = (const float*)d_in[3];
    const float* Wp   = (const float*)d_in[4];
    const float* bias = (const float*)d_in[5];
    float* out = (float*)d_out;

    const int attn_smem = (3 * 64 * QS + 64 * 64) * (int)sizeof(float);  // 68608 B
    cudaFuncSetAttribute(attn_kernel, cudaFuncAttributeMaxDynamicSharedMemorySize, attn_smem);
    cudaFuncSetAttribute(gemm_kernel<0>, cudaFuncAttributeMaxDynamicSharedMemorySize, GEMM_SMEM);
    cudaFuncSetAttribute(gemm_kernel<1>, cudaFuncAttributeMaxDynamicSharedMemorySize, GEMM_SMEM);

    // 1) precision-split conversions
    convx_kernel<<<M_*C_/4/256, 256>>>(x);
    convw_kernel<<<dim3(16, 32), 256>>>(Wq, 0);
    convw_kernel<<<dim3(16, 32), 256>>>(Wk, 1024);
    convw_kernel<<<dim3(16, 32), 256>>>(Wv, 2048);
    convwp_kernel<<<dim3(32, 32), 256>>>(Wp);

    // 2) QKV projection (HMMA tensor path)
    gemm_kernel<0><<<dim3(64, 24), 256, GEMM_SMEM>>>(nullptr, nullptr);

    // 3) causal attention (fp32 SIMT)
    attn_kernel<<<dim3(16, 16, 8), 256, attn_smem>>>();

    // 4) output projection (HMMA) + bias
    gemm_kernel<1><<<dim3(64, 8), 256, GEMM_SMEM>>>(bias, out);
}